// round 6
// baseline (speedup 1.0000x reference)
#include <cuda_runtime.h>
#include <cuda_bf16.h>
#include <cstdint>
#include <cstddef>

#define NPTS 8192
#define DIM  1024
typedef __nv_bfloat16 bf16;

#define AL __align__(256)
__device__ AL bf16 g_ph[(size_t)NPTS * DIM], g_pl[(size_t)NPTS * DIM];
__device__ AL bf16 g_rh[(size_t)NPTS * DIM], g_rl[(size_t)NPTS * DIM];
__device__ AL bf16 g_Whh[(size_t)DIM * DIM], g_Whl[(size_t)DIM * DIM];
__device__ AL bf16 g_Wlh[(size_t)DIM * DIM], g_Wll[(size_t)DIM * DIM];
__device__ AL bf16 g_Wgh[(size_t)DIM * DIM], g_Wgl[(size_t)DIM * DIM];
__device__ AL bf16 g_Qh[(size_t)NPTS * DIM], g_Ql[(size_t)NPTS * DIM];
__device__ AL bf16 g_Kh[(size_t)NPTS * DIM], g_Kl[(size_t)NPTS * DIM];
__device__ AL float g_V[(size_t)NPTS * DIM];
__device__ AL bf16 g_VTh[(size_t)DIM * NPTS], g_VTl[(size_t)DIM * NPTS];
__device__ AL bf16 g_Eh[(size_t)NPTS * NPTS], g_El[(size_t)NPTS * NPTS];
__device__ AL float g_csum[16 * NPTS];
__device__ AL float g_rc[NPTS];

__device__ __forceinline__ uint32_t smem_u32(const void* p) {
    uint32_t a;
    asm("{ .reg .u64 t; cvta.to.shared.u64 t, %1; cvt.u32.u64 %0, t; }" : "=r"(a) : "l"(p));
    return a;
}
__device__ __forceinline__ void cp16(uint32_t dst, const void* src) {
    asm volatile("cp.async.cg.shared.global [%0], [%1], 16;"
                 :: "r"(dst), "l"(__cvta_generic_to_global(src)) : "memory");
}
__device__ __forceinline__ void ldmx4(uint32_t* r, uint32_t addr) {
    asm volatile("ldmatrix.sync.aligned.m8n8.x4.shared.b16 {%0,%1,%2,%3}, [%4];"
                 : "=r"(r[0]), "=r"(r[1]), "=r"(r[2]), "=r"(r[3]) : "r"(addr));
}
__device__ __forceinline__ void mma16816(float* c, const uint32_t* a, const uint32_t* b) {
    asm volatile("mma.sync.aligned.m16n8k16.row.col.f32.bf16.bf16.f32 "
                 "{%0,%1,%2,%3}, {%4,%5,%6,%7}, {%8,%9}, {%0,%1,%2,%3};"
                 : "+f"(c[0]), "+f"(c[1]), "+f"(c[2]), "+f"(c[3])
                 : "r"(a[0]), "r"(a[1]), "r"(a[2]), "r"(a[3]), "r"(b[0]), "r"(b[1]));
}

// Tile: 128x128, BK=32 bf16 (64B rows). Swizzle: 16B chunk ^= (row>>1)&3.
// Stage: Ahi 8K | Alo 8K | Bhi 8K | Blo 8K = 32 KB; 3 stages (96 KB).
#define BK 32
#define STG 32768u
#define NSTG 3
#define GSMEM (NSTG * STG)
#define T_AHI 0u
#define T_ALO 8192u
#define T_BHI 16384u
#define T_BLO 24576u

__device__ __forceinline__ uint32_t swz(int row, int chunk) {
    return (uint32_t)(row * 64 + ((chunk ^ ((row >> 1) & 3)) << 4));
}

// MODE 0: bias+fp32 | 1: bias+bf16 split | 2: exp+bf16 split | 3: residual fp32
template <int MODE>
__global__ __launch_bounds__(256, 2) void gemm_mma(
    const bf16* __restrict__ Ahi, const bf16* __restrict__ Alo,
    const bf16* __restrict__ Bhi, const bf16* __restrict__ Blo,
    int Kd, int ldC, const float* __restrict__ bias, const float* __restrict__ P0,
    float* __restrict__ Cf, bf16* __restrict__ Chi, bf16* __restrict__ Clo)
{
    extern __shared__ char smraw[];
    const uint32_t sm0 = smem_u32(smraw);
    const int tid = threadIdx.x, lane = tid & 31, warp = tid >> 5;
    const int wm = warp >> 1, wn = warp & 1;           // 4 x 2 warp grid
    const int row0 = blockIdx.y * 128, col0 = blockIdx.x * 128;

    // per-thread ldmatrix offsets (within a tile)
    uint32_t aoff[2][2], boff[4][2];
#pragma unroll
    for (int mi = 0; mi < 2; mi++)
#pragma unroll
        for (int ks = 0; ks < 2; ks++) {
            const int r = wm * 32 + mi * 16 + (lane & 15);
            aoff[mi][ks] = swz(r, ks * 2 + (lane >> 4));
        }
#pragma unroll
    for (int np = 0; np < 4; np++)
#pragma unroll
        for (int ks = 0; ks < 2; ks++) {
            const int r = wn * 64 + np * 16 + (lane & 7) + ((lane >> 4) & 1) * 8;
            boff[np][ks] = swz(r, ks * 2 + ((lane >> 3) & 1));
        }

    // cp.async mapping: id = i*256+tid -> row=id>>2, chunk=id&3
    const int ldr = tid >> 2, ldc = tid & 3;

    auto load_stage = [&](int kb, int st) {
        const int k0 = kb * BK;
        const uint32_t s = sm0 + (uint32_t)st * STG;
#pragma unroll
        for (int i = 0; i < 2; i++) {
            const int row = ldr + i * 64;
            const uint32_t d = swz(row, ldc);
            const size_t ga = (size_t)(row0 + row) * Kd + k0 + ldc * 8;
            const size_t gb = (size_t)(col0 + row) * Kd + k0 + ldc * 8;
            cp16(s + T_AHI + d, Ahi + ga);
            cp16(s + T_ALO + d, Alo + ga);
            cp16(s + T_BHI + d, Bhi + gb);
            cp16(s + T_BLO + d, Blo + gb);
        }
    };

    float acc[2][8][4];
#pragma unroll
    for (int mi = 0; mi < 2; mi++)
#pragma unroll
        for (int ni = 0; ni < 8; ni++)
#pragma unroll
            for (int q = 0; q < 4; q++) acc[mi][ni][q] = 0.f;

    const int nkb = Kd / BK;
    load_stage(0, 0);
    asm volatile("cp.async.commit_group;" ::: "memory");
    load_stage(1, 1);
    asm volatile("cp.async.commit_group;" ::: "memory");

    int st = 0, pf = 2;   // current stage, prefetch stage
    for (int kb = 0; kb < nkb; kb++) {
        asm volatile("cp.async.wait_group 1;" ::: "memory");
        __syncthreads();
        // prefetch kb+2 into stage pf (its last readers were fenced by the sync)
        if (kb + 2 < nkb) load_stage(kb + 2, pf);
        asm volatile("cp.async.commit_group;" ::: "memory");

        const uint32_t s = sm0 + (uint32_t)st * STG;
#pragma unroll
        for (int ks = 0; ks < 2; ks++) {
            uint32_t ah[2][4], al[2][4];
#pragma unroll
            for (int mi = 0; mi < 2; mi++) {
                ldmx4(ah[mi], s + T_AHI + aoff[mi][ks]);
                ldmx4(al[mi], s + T_ALO + aoff[mi][ks]);
            }
            // consume B fragments immediately after load: peak live B regs = 8
#pragma unroll
            for (int np = 0; np < 4; np++) {
                uint32_t tbh[4], tbl[4];
                ldmx4(tbh, s + T_BHI + boff[np][ks]);
                ldmx4(tbl, s + T_BLO + boff[np][ks]);
#pragma unroll
                for (int nn = 0; nn < 2; nn++) {
                    const int ni = np * 2 + nn;
#pragma unroll
                    for (int mi = 0; mi < 2; mi++) {
                        mma16816(acc[mi][ni], ah[mi], tbh + nn * 2);
                        mma16816(acc[mi][ni], ah[mi], tbl + nn * 2);
                        mma16816(acc[mi][ni], al[mi], tbh + nn * 2);
                    }
                }
            }
        }
        st = (st == NSTG - 1) ? 0 : st + 1;
        pf = (pf == NSTG - 1) ? 0 : pf + 1;
    }

    // Epilogue: frag (mi, ni): rows m0,m0+8; cols c0,c0+1
#pragma unroll
    for (int mi = 0; mi < 2; mi++)
#pragma unroll
        for (int ni = 0; ni < 8; ni++) {
            const int m0 = row0 + wm * 32 + mi * 16 + (lane >> 2);
            const int c  = col0 + wn * 64 + ni * 8 + (lane & 3) * 2;
#pragma unroll
            for (int h = 0; h < 2; h++) {
                const int m = m0 + h * 8;
                float v0 = acc[mi][ni][2 * h], v1 = acc[mi][ni][2 * h + 1];
                if (MODE == 0) {
                    float2* dst = (float2*)&Cf[(size_t)m * ldC + c];
                    *dst = make_float2(v0 + bias[c], v1 + bias[c + 1]);
                } else if (MODE == 3) {
                    const float2 pp = *(const float2*)&P0[(size_t)m * ldC + c];
                    float2* dst = (float2*)&Cf[(size_t)m * ldC + c];
                    *dst = make_float2(v0 + pp.x, v1 + pp.y);
                } else {
                    if (MODE == 1) { v0 += bias[c]; v1 += bias[c + 1]; }
                    else { v0 = __expf(v0); v1 = __expf(v1); }
                    bf16 h0 = __float2bfloat16(v0), h1 = __float2bfloat16(v1);
                    *(__nv_bfloat162*)&Chi[(size_t)m * ldC + c] = __nv_bfloat162(h0, h1);
                    *(__nv_bfloat162*)&Clo[(size_t)m * ldC + c] =
                        __nv_bfloat162(__float2bfloat16(v0 - __bfloat162float(h0)),
                                       __float2bfloat16(v1 - __bfloat162float(h1)));
                }
            }
        }
}

__global__ __launch_bounds__(256) void split_kernel(
    const float4* __restrict__ x, __nv_bfloat162* __restrict__ hi,
    __nv_bfloat162* __restrict__ lo, int n4)
{
    int i = blockIdx.x * 256 + threadIdx.x;
    if (i >= n4) return;
    float4 v = x[i];
    bf16 h0 = __float2bfloat16(v.x), h1 = __float2bfloat16(v.y);
    bf16 h2 = __float2bfloat16(v.z), h3 = __float2bfloat16(v.w);
    hi[2*i]   = __nv_bfloat162(h0, h1);
    hi[2*i+1] = __nv_bfloat162(h2, h3);
    lo[2*i]   = __nv_bfloat162(__float2bfloat16(v.x - __bfloat162float(h0)),
                               __float2bfloat16(v.y - __bfloat162float(h1)));
    lo[2*i+1] = __nv_bfloat162(__float2bfloat16(v.z - __bfloat162float(h2)),
                               __float2bfloat16(v.w - __bfloat162float(h3)));
}

__global__ __launch_bounds__(256) void colsum_kernel(
    const bf16* __restrict__ Eh, const bf16* __restrict__ El, float* __restrict__ csum)
{
    const int j = blockIdx.x * 256 + threadIdx.x;
    const size_t i0 = (size_t)blockIdx.y * (NPTS / 16);
    float c = 0.f;
    for (int t = 0; t < NPTS / 16; t++) {
        const size_t idx = (i0 + t) * NPTS + j;
        c += __bfloat162float(Eh[idx]) + __bfloat162float(El[idx]);
    }
    csum[(size_t)blockIdx.y * NPTS + j] = c;
}

__global__ __launch_bounds__(256) void rc_kernel(
    const float* __restrict__ csum, float* __restrict__ rc)
{
    const int j = blockIdx.x * 256 + threadIdx.x;
    float c = 0.f;
#pragma unroll
    for (int h = 0; h < 16; h++) c += csum[(size_t)h * NPTS + j];
    rc[j] = 1.0f / c;
}

__global__ __launch_bounds__(256) void vt_kernel(
    const float* __restrict__ V, const float* __restrict__ rc,
    bf16* __restrict__ VTh, bf16* __restrict__ VTl)
{
    __shared__ float t[32][33];
    const int tx = threadIdx.x, ty = threadIdx.y;
    const int d0 = blockIdx.x * 32, j0 = blockIdx.y * 32;
#pragma unroll
    for (int q = 0; q < 4; q++) {
        const int j = j0 + ty + q * 8;
        t[ty + q * 8][tx] = V[(size_t)j * DIM + d0 + tx] * rc[j];
    }
    __syncthreads();
#pragma unroll
    for (int q = 0; q < 4; q++) {
        const int d = d0 + ty + q * 8, j = j0 + tx;
        float v = t[tx][ty + q * 8];
        bf16 h = __float2bfloat16(v);
        VTh[(size_t)d * NPTS + j] = h;
        VTl[(size_t)d * NPTS + j] = __float2bfloat16(v - __bfloat162float(h));
    }
}

extern "C" void kernel_launch(void* const* d_in, const int* in_sizes, int n_in,
                              void* d_out, int out_size)
{
    const float* p  = (const float*)d_in[0];
    const float* r  = (const float*)d_in[1];
    const float* Wh = (const float*)d_in[2];
    const float* bh = (const float*)d_in[3];
    const float* Wl = (const float*)d_in[4];
    const float* bl = (const float*)d_in[5];
    const float* Wg = (const float*)d_in[6];
    const float* bg = (const float*)d_in[7];
    float* out = (float*)d_out;

    bf16 *ph_, *pl_, *rh_, *rl_, *Whh, *Whl, *Wlh, *Wll, *Wgh, *Wgl;
    bf16 *Qh, *Ql, *Kh, *Kl, *VTh, *VTl, *Eh, *El;
    float *V, *csum, *rc;
    cudaGetSymbolAddress((void**)&ph_, g_ph);  cudaGetSymbolAddress((void**)&pl_, g_pl);
    cudaGetSymbolAddress((void**)&rh_, g_rh);  cudaGetSymbolAddress((void**)&rl_, g_rl);
    cudaGetSymbolAddress((void**)&Whh, g_Whh); cudaGetSymbolAddress((void**)&Whl, g_Whl);
    cudaGetSymbolAddress((void**)&Wlh, g_Wlh); cudaGetSymbolAddress((void**)&Wll, g_Wll);
    cudaGetSymbolAddress((void**)&Wgh, g_Wgh); cudaGetSymbolAddress((void**)&Wgl, g_Wgl);
    cudaGetSymbolAddress((void**)&Qh, g_Qh);   cudaGetSymbolAddress((void**)&Ql, g_Ql);
    cudaGetSymbolAddress((void**)&Kh, g_Kh);   cudaGetSymbolAddress((void**)&Kl, g_Kl);
    cudaGetSymbolAddress((void**)&V, g_V);
    cudaGetSymbolAddress((void**)&VTh, g_VTh); cudaGetSymbolAddress((void**)&VTl, g_VTl);
    cudaGetSymbolAddress((void**)&Eh, g_Eh);   cudaGetSymbolAddress((void**)&El, g_El);
    cudaGetSymbolAddress((void**)&csum, g_csum); cudaGetSymbolAddress((void**)&rc, g_rc);

    cudaFuncSetAttribute(gemm_mma<0>, cudaFuncAttributeMaxDynamicSharedMemorySize, GSMEM);
    cudaFuncSetAttribute(gemm_mma<1>, cudaFuncAttributeMaxDynamicSharedMemorySize, GSMEM);
    cudaFuncSetAttribute(gemm_mma<2>, cudaFuncAttributeMaxDynamicSharedMemorySize, GSMEM);
    cudaFuncSetAttribute(gemm_mma<3>, cudaFuncAttributeMaxDynamicSharedMemorySize, GSMEM);

    const int nPD4 = NPTS * DIM / 4, nDD4 = DIM * DIM / 4;
    split_kernel<<<nPD4/256, 256>>>((const float4*)p, (__nv_bfloat162*)ph_, (__nv_bfloat162*)pl_, nPD4);
    split_kernel<<<nPD4/256, 256>>>((const float4*)r, (__nv_bfloat162*)rh_, (__nv_bfloat162*)rl_, nPD4);
    split_kernel<<<nDD4/256, 256>>>((const float4*)Wh, (__nv_bfloat162*)Whh, (__nv_bfloat162*)Whl, nDD4);
    split_kernel<<<nDD4/256, 256>>>((const float4*)Wl, (__nv_bfloat162*)Wlh, (__nv_bfloat162*)Wll, nDD4);
    split_kernel<<<nDD4/256, 256>>>((const float4*)Wg, (__nv_bfloat162*)Wgh, (__nv_bfloat162*)Wgl, nDD4);

    dim3 gproj(DIM/128, NPTS/128);
    gemm_mma<1><<<gproj, 256, GSMEM>>>(ph_, pl_, Whh, Whl, DIM, DIM, bh, nullptr, nullptr, Qh, Ql);
    gemm_mma<1><<<gproj, 256, GSMEM>>>(rh_, rl_, Wlh, Wll, DIM, DIM, bl, nullptr, nullptr, Kh, Kl);
    gemm_mma<0><<<gproj, 256, GSMEM>>>(ph_, pl_, Wgh, Wgl, DIM, DIM, bg, nullptr, V, nullptr, nullptr);

    dim3 gS(NPTS/128, NPTS/128);
    gemm_mma<2><<<gS, 256, GSMEM>>>(Qh, Ql, Kh, Kl, DIM, NPTS, nullptr, nullptr, nullptr, Eh, El);

    colsum_kernel<<<dim3(NPTS/256, 16), 256>>>(Eh, El, csum);
    rc_kernel<<<NPTS/256, 256>>>(csum, rc);
    vt_kernel<<<dim3(DIM/32, NPTS/32), dim3(32, 8)>>>(V, rc, VTh, VTl);

    dim3 gpv(DIM/128, NPTS/128);
    gemm_mma<3><<<gpv, 256, GSMEM>>>(Eh, El, VTh, VTl, NPTS, DIM, nullptr, p, out, nullptr, nullptr);
}

// round 7
// speedup vs baseline: 1.0585x; 1.0585x over previous
#include <cuda_runtime.h>
#include <cuda_bf16.h>
#include <cstdint>
#include <cstddef>

#define NPTS 8192
#define DIM  1024
typedef __nv_bfloat16 bf16;

#define AL __align__(256)
__device__ AL bf16 g_ph[(size_t)NPTS * DIM], g_pl[(size_t)NPTS * DIM];
__device__ AL bf16 g_rh[(size_t)NPTS * DIM], g_rl[(size_t)NPTS * DIM];
__device__ AL bf16 g_Whh[(size_t)DIM * DIM], g_Whl[(size_t)DIM * DIM];
__device__ AL bf16 g_Wlh[(size_t)DIM * DIM], g_Wll[(size_t)DIM * DIM];
__device__ AL bf16 g_Wgh[(size_t)DIM * DIM], g_Wgl[(size_t)DIM * DIM];
__device__ AL bf16 g_Qh[(size_t)NPTS * DIM], g_Ql[(size_t)NPTS * DIM];
__device__ AL bf16 g_Kh[(size_t)NPTS * DIM], g_Kl[(size_t)NPTS * DIM];
__device__ AL float g_V[(size_t)NPTS * DIM];
__device__ AL bf16 g_VTh[(size_t)DIM * NPTS], g_VTl[(size_t)DIM * NPTS];
__device__ AL bf16 g_Eh[(size_t)NPTS * NPTS], g_El[(size_t)NPTS * NPTS];
__device__ AL float g_csum[16 * NPTS];
__device__ AL float g_rc[NPTS];

__device__ __forceinline__ uint32_t smem_u32(const void* p) {
    uint32_t a;
    asm("{ .reg .u64 t; cvta.to.shared.u64 t, %1; cvt.u32.u64 %0, t; }" : "=r"(a) : "l"(p));
    return a;
}
__device__ __forceinline__ void cp16(uint32_t dst, const void* src) {
    asm volatile("cp.async.cg.shared.global [%0], [%1], 16;"
                 :: "r"(dst), "l"(__cvta_generic_to_global(src)) : "memory");
}
__device__ __forceinline__ void ldmx4(uint32_t* r, uint32_t addr) {
    asm volatile("ldmatrix.sync.aligned.m8n8.x4.shared.b16 {%0,%1,%2,%3}, [%4];"
                 : "=r"(r[0]), "=r"(r[1]), "=r"(r[2]), "=r"(r[3]) : "r"(addr));
}
__device__ __forceinline__ void mma16816(float* c, const uint32_t* a, const uint32_t* b) {
    asm volatile("mma.sync.aligned.m16n8k16.row.col.f32.bf16.bf16.f32 "
                 "{%0,%1,%2,%3}, {%4,%5,%6,%7}, {%8,%9}, {%0,%1,%2,%3};"
                 : "+f"(c[0]), "+f"(c[1]), "+f"(c[2]), "+f"(c[3])
                 : "r"(a[0]), "r"(a[1]), "r"(a[2]), "r"(a[3]), "r"(b[0]), "r"(b[1]));
}

// Tile: 128x128, BK=32 bf16 (64B rows). Swizzle: 16B chunk ^= (row>>1)&3.
// Stage: Ahi 8K | Alo 8K | Bhi 8K | Blo 8K = 32 KB; 3 stages (96 KB).
#define BK 32
#define STG 32768u
#define NSTG 3
#define GSMEM (NSTG * STG)
#define T_AHI 0u
#define T_ALO 8192u
#define T_BHI 16384u
#define T_BLO 24576u

__device__ __forceinline__ uint32_t swz(int row, int chunk) {
    return (uint32_t)(row * 64 + ((chunk ^ ((row >> 1) & 3)) << 4));
}

// MODE 0: bias+fp32 | 1: bias+bf16 split | 2: exp+bf16 split | 3: residual fp32
template <int MODE>
__global__ __launch_bounds__(256, 2) void gemm_mma(
    const bf16* __restrict__ Ahi, const bf16* __restrict__ Alo,
    const bf16* __restrict__ Bhi, const bf16* __restrict__ Blo,
    int Kd, int ldC, const float* __restrict__ bias, const float* __restrict__ P0,
    float* __restrict__ Cf, bf16* __restrict__ Chi, bf16* __restrict__ Clo)
{
    extern __shared__ char smraw[];
    const uint32_t sm0 = smem_u32(smraw);
    const int tid = threadIdx.x, lane = tid & 31, warp = tid >> 5;
    const int wm = warp >> 1, wn = warp & 1;           // 4 x 2 warp grid
    const int row0 = blockIdx.y * 128, col0 = blockIdx.x * 128;

    // per-thread ldmatrix offsets (within a tile)
    uint32_t aoff[2][2], boff[4][2];
#pragma unroll
    for (int mi = 0; mi < 2; mi++)
#pragma unroll
        for (int ks = 0; ks < 2; ks++) {
            const int r = wm * 32 + mi * 16 + (lane & 15);
            aoff[mi][ks] = swz(r, ks * 2 + (lane >> 4));
        }
#pragma unroll
    for (int np = 0; np < 4; np++)
#pragma unroll
        for (int ks = 0; ks < 2; ks++) {
            const int r = wn * 64 + np * 16 + (lane & 7) + ((lane >> 4) & 1) * 8;
            boff[np][ks] = swz(r, ks * 2 + ((lane >> 3) & 1));
        }

    // cp.async mapping: id = i*256+tid -> row=id>>2, chunk=id&3
    const int ldr = tid >> 2, ldc = tid & 3;

    auto load_stage = [&](int kb, int st) {
        const int k0 = kb * BK;
        const uint32_t s = sm0 + (uint32_t)st * STG;
#pragma unroll
        for (int i = 0; i < 2; i++) {
            const int row = ldr + i * 64;
            const uint32_t d = swz(row, ldc);
            const size_t ga = (size_t)(row0 + row) * Kd + k0 + ldc * 8;
            const size_t gb = (size_t)(col0 + row) * Kd + k0 + ldc * 8;
            cp16(s + T_AHI + d, Ahi + ga);
            cp16(s + T_ALO + d, Alo + ga);
            cp16(s + T_BHI + d, Bhi + gb);
            cp16(s + T_BLO + d, Blo + gb);
        }
    };

    float acc[2][8][4];
#pragma unroll
    for (int mi = 0; mi < 2; mi++)
#pragma unroll
        for (int ni = 0; ni < 8; ni++)
#pragma unroll
            for (int q = 0; q < 4; q++) acc[mi][ni][q] = 0.f;

    const int nkb = Kd / BK;
    load_stage(0, 0);
    asm volatile("cp.async.commit_group;" ::: "memory");
    load_stage(1, 1);
    asm volatile("cp.async.commit_group;" ::: "memory");

    int st = 0, pf = 2;   // current stage, prefetch stage
    for (int kb = 0; kb < nkb; kb++) {
        asm volatile("cp.async.wait_group 1;" ::: "memory");
        __syncthreads();
        // prefetch kb+2 into stage pf (its last readers were fenced by the sync)
        if (kb + 2 < nkb) load_stage(kb + 2, pf);
        asm volatile("cp.async.commit_group;" ::: "memory");

        const uint32_t s = sm0 + (uint32_t)st * STG;
#pragma unroll
        for (int ks = 0; ks < 2; ks++) {
            uint32_t ah[2][4], al[2][4], bh[8][2], bl[8][2];
#pragma unroll
            for (int mi = 0; mi < 2; mi++) {
                ldmx4(ah[mi], s + T_AHI + aoff[mi][ks]);
                ldmx4(al[mi], s + T_ALO + aoff[mi][ks]);
            }
#pragma unroll
            for (int np = 0; np < 4; np++) {
                uint32_t t[4];
                ldmx4(t, s + T_BHI + boff[np][ks]);
                bh[np*2][0] = t[0]; bh[np*2][1] = t[1];
                bh[np*2+1][0] = t[2]; bh[np*2+1][1] = t[3];
                ldmx4(t, s + T_BLO + boff[np][ks]);
                bl[np*2][0] = t[0]; bl[np*2][1] = t[1];
                bl[np*2+1][0] = t[2]; bl[np*2+1][1] = t[3];
            }
            // product-type outermost: 16 independent acc chains per sweep,
            // accumulator reuse distance = 16 MMAs (vs 1 in the old order)
#pragma unroll
            for (int mi = 0; mi < 2; mi++)
#pragma unroll
                for (int ni = 0; ni < 8; ni++)
                    mma16816(acc[mi][ni], ah[mi], bh[ni]);
#pragma unroll
            for (int mi = 0; mi < 2; mi++)
#pragma unroll
                for (int ni = 0; ni < 8; ni++)
                    mma16816(acc[mi][ni], ah[mi], bl[ni]);
#pragma unroll
            for (int mi = 0; mi < 2; mi++)
#pragma unroll
                for (int ni = 0; ni < 8; ni++)
                    mma16816(acc[mi][ni], al[mi], bh[ni]);
        }
        st = (st == NSTG - 1) ? 0 : st + 1;
        pf = (pf == NSTG - 1) ? 0 : pf + 1;
    }

    // Epilogue: frag (mi, ni): rows m0,m0+8; cols c0,c0+1
#pragma unroll
    for (int mi = 0; mi < 2; mi++)
#pragma unroll
        for (int ni = 0; ni < 8; ni++) {
            const int m0 = row0 + wm * 32 + mi * 16 + (lane >> 2);
            const int c  = col0 + wn * 64 + ni * 8 + (lane & 3) * 2;
#pragma unroll
            for (int h = 0; h < 2; h++) {
                const int m = m0 + h * 8;
                float v0 = acc[mi][ni][2 * h], v1 = acc[mi][ni][2 * h + 1];
                if (MODE == 0) {
                    float2* dst = (float2*)&Cf[(size_t)m * ldC + c];
                    *dst = make_float2(v0 + bias[c], v1 + bias[c + 1]);
                } else if (MODE == 3) {
                    const float2 pp = *(const float2*)&P0[(size_t)m * ldC + c];
                    float2* dst = (float2*)&Cf[(size_t)m * ldC + c];
                    *dst = make_float2(v0 + pp.x, v1 + pp.y);
                } else {
                    if (MODE == 1) { v0 += bias[c]; v1 += bias[c + 1]; }
                    else { v0 = __expf(v0); v1 = __expf(v1); }
                    bf16 h0 = __float2bfloat16(v0), h1 = __float2bfloat16(v1);
                    *(__nv_bfloat162*)&Chi[(size_t)m * ldC + c] = __nv_bfloat162(h0, h1);
                    *(__nv_bfloat162*)&Clo[(size_t)m * ldC + c] =
                        __nv_bfloat162(__float2bfloat16(v0 - __bfloat162float(h0)),
                                       __float2bfloat16(v1 - __bfloat162float(h1)));
                }
            }
        }
}

__global__ __launch_bounds__(256) void split_kernel(
    const float4* __restrict__ x, __nv_bfloat162* __restrict__ hi,
    __nv_bfloat162* __restrict__ lo, int n4)
{
    int i = blockIdx.x * 256 + threadIdx.x;
    if (i >= n4) return;
    float4 v = x[i];
    bf16 h0 = __float2bfloat16(v.x), h1 = __float2bfloat16(v.y);
    bf16 h2 = __float2bfloat16(v.z), h3 = __float2bfloat16(v.w);
    hi[2*i]   = __nv_bfloat162(h0, h1);
    hi[2*i+1] = __nv_bfloat162(h2, h3);
    lo[2*i]   = __nv_bfloat162(__float2bfloat16(v.x - __bfloat162float(h0)),
                               __float2bfloat16(v.y - __bfloat162float(h1)));
    lo[2*i+1] = __nv_bfloat162(__float2bfloat16(v.z - __bfloat162float(h2)),
                               __float2bfloat16(v.w - __bfloat162float(h3)));
}

__global__ __launch_bounds__(256) void colsum_kernel(
    const bf16* __restrict__ Eh, const bf16* __restrict__ El, float* __restrict__ csum)
{
    const int j = blockIdx.x * 256 + threadIdx.x;
    const size_t i0 = (size_t)blockIdx.y * (NPTS / 16);
    float c = 0.f;
    for (int t = 0; t < NPTS / 16; t++) {
        const size_t idx = (i0 + t) * NPTS + j;
        c += __bfloat162float(Eh[idx]) + __bfloat162float(El[idx]);
    }
    csum[(size_t)blockIdx.y * NPTS + j] = c;
}

__global__ __launch_bounds__(256) void rc_kernel(
    const float* __restrict__ csum, float* __restrict__ rc)
{
    const int j = blockIdx.x * 256 + threadIdx.x;
    float c = 0.f;
#pragma unroll
    for (int h = 0; h < 16; h++) c += csum[(size_t)h * NPTS + j];
    rc[j] = 1.0f / c;
}

__global__ __launch_bounds__(256) void vt_kernel(
    const float* __restrict__ V, const float* __restrict__ rc,
    bf16* __restrict__ VTh, bf16* __restrict__ VTl)
{
    __shared__ float t[32][33];
    const int tx = threadIdx.x, ty = threadIdx.y;
    const int d0 = blockIdx.x * 32, j0 = blockIdx.y * 32;
#pragma unroll
    for (int q = 0; q < 4; q++) {
        const int j = j0 + ty + q * 8;
        t[ty + q * 8][tx] = V[(size_t)j * DIM + d0 + tx] * rc[j];
    }
    __syncthreads();
#pragma unroll
    for (int q = 0; q < 4; q++) {
        const int d = d0 + ty + q * 8, j = j0 + tx;
        float v = t[tx][ty + q * 8];
        bf16 h = __float2bfloat16(v);
        VTh[(size_t)d * NPTS + j] = h;
        VTl[(size_t)d * NPTS + j] = __float2bfloat16(v - __bfloat162float(h));
    }
}

extern "C" void kernel_launch(void* const* d_in, const int* in_sizes, int n_in,
                              void* d_out, int out_size)
{
    const float* p  = (const float*)d_in[0];
    const float* r  = (const float*)d_in[1];
    const float* Wh = (const float*)d_in[2];
    const float* bh = (const float*)d_in[3];
    const float* Wl = (const float*)d_in[4];
    const float* bl = (const float*)d_in[5];
    const float* Wg = (const float*)d_in[6];
    const float* bg = (const float*)d_in[7];
    float* out = (float*)d_out;

    bf16 *ph_, *pl_, *rh_, *rl_, *Whh, *Whl, *Wlh, *Wll, *Wgh, *Wgl;
    bf16 *Qh, *Ql, *Kh, *Kl, *VTh, *VTl, *Eh, *El;
    float *V, *csum, *rc;
    cudaGetSymbolAddress((void**)&ph_, g_ph);  cudaGetSymbolAddress((void**)&pl_, g_pl);
    cudaGetSymbolAddress((void**)&rh_, g_rh);  cudaGetSymbolAddress((void**)&rl_, g_rl);
    cudaGetSymbolAddress((void**)&Whh, g_Whh); cudaGetSymbolAddress((void**)&Whl, g_Whl);
    cudaGetSymbolAddress((void**)&Wlh, g_Wlh); cudaGetSymbolAddress((void**)&Wll, g_Wll);
    cudaGetSymbolAddress((void**)&Wgh, g_Wgh); cudaGetSymbolAddress((void**)&Wgl, g_Wgl);
    cudaGetSymbolAddress((void**)&Qh, g_Qh);   cudaGetSymbolAddress((void**)&Ql, g_Ql);
    cudaGetSymbolAddress((void**)&Kh, g_Kh);   cudaGetSymbolAddress((void**)&Kl, g_Kl);
    cudaGetSymbolAddress((void**)&V, g_V);
    cudaGetSymbolAddress((void**)&VTh, g_VTh); cudaGetSymbolAddress((void**)&VTl, g_VTl);
    cudaGetSymbolAddress((void**)&Eh, g_Eh);   cudaGetSymbolAddress((void**)&El, g_El);
    cudaGetSymbolAddress((void**)&csum, g_csum); cudaGetSymbolAddress((void**)&rc, g_rc);

    cudaFuncSetAttribute(gemm_mma<0>, cudaFuncAttributeMaxDynamicSharedMemorySize, GSMEM);
    cudaFuncSetAttribute(gemm_mma<1>, cudaFuncAttributeMaxDynamicSharedMemorySize, GSMEM);
    cudaFuncSetAttribute(gemm_mma<2>, cudaFuncAttributeMaxDynamicSharedMemorySize, GSMEM);
    cudaFuncSetAttribute(gemm_mma<3>, cudaFuncAttributeMaxDynamicSharedMemorySize, GSMEM);

    const int nPD4 = NPTS * DIM / 4, nDD4 = DIM * DIM / 4;
    split_kernel<<<nPD4/256, 256>>>((const float4*)p, (__nv_bfloat162*)ph_, (__nv_bfloat162*)pl_, nPD4);
    split_kernel<<<nPD4/256, 256>>>((const float4*)r, (__nv_bfloat162*)rh_, (__nv_bfloat162*)rl_, nPD4);
    split_kernel<<<nDD4/256, 256>>>((const float4*)Wh, (__nv_bfloat162*)Whh, (__nv_bfloat162*)Whl, nDD4);
    split_kernel<<<nDD4/256, 256>>>((const float4*)Wl, (__nv_bfloat162*)Wlh, (__nv_bfloat162*)Wll, nDD4);
    split_kernel<<<nDD4/256, 256>>>((const float4*)Wg, (__nv_bfloat162*)Wgh, (__nv_bfloat162*)Wgl, nDD4);

    dim3 gproj(DIM/128, NPTS/128);
    gemm_mma<1><<<gproj, 256, GSMEM>>>(ph_, pl_, Whh, Whl, DIM, DIM, bh, nullptr, nullptr, Qh, Ql);
    gemm_mma<1><<<gproj, 256, GSMEM>>>(rh_, rl_, Wlh, Wll, DIM, DIM, bl, nullptr, nullptr, Kh, Kl);
    gemm_mma<0><<<gproj, 256, GSMEM>>>(ph_, pl_, Wgh, Wgl, DIM, DIM, bg, nullptr, V, nullptr, nullptr);

    dim3 gS(NPTS/128, NPTS/128);
    gemm_mma<2><<<gS, 256, GSMEM>>>(Qh, Ql, Kh, Kl, DIM, NPTS, nullptr, nullptr, nullptr, Eh, El);

    colsum_kernel<<<dim3(NPTS/256, 16), 256>>>(Eh, El, csum);
    rc_kernel<<<NPTS/256, 256>>>(csum, rc);
    vt_kernel<<<dim3(DIM/32, NPTS/32), dim3(32, 8)>>>(V, rc, VTh, VTl);

    dim3 gpv(DIM/128, NPTS/128);
    gemm_mma<3><<<gpv, 256, GSMEM>>>(Eh, El, VTh, VTl, NPTS, DIM, nullptr, p, out, nullptr, nullptr);
}

// round 9
// speedup vs baseline: 1.4755x; 1.3940x over previous
#include <cuda_runtime.h>
#include <cuda_bf16.h>
#include <cstdint>
#include <cstddef>

#define NPTS 8192
#define DIM  1024
typedef __nv_bfloat16 bf16;

#define AL __align__(256)
__device__ AL bf16 g_ph[(size_t)NPTS * DIM], g_pl[(size_t)NPTS * DIM];
__device__ AL bf16 g_rh[(size_t)NPTS * DIM], g_rl[(size_t)NPTS * DIM];
__device__ AL bf16 g_Whh[(size_t)DIM * DIM], g_Whl[(size_t)DIM * DIM];
__device__ AL bf16 g_Wlh[(size_t)DIM * DIM], g_Wll[(size_t)DIM * DIM];
__device__ AL bf16 g_Wgh[(size_t)DIM * DIM], g_Wgl[(size_t)DIM * DIM];
__device__ AL bf16 g_Qh[(size_t)NPTS * DIM], g_Ql[(size_t)NPTS * DIM];
__device__ AL bf16 g_Kh[(size_t)NPTS * DIM], g_Kl[(size_t)NPTS * DIM];
__device__ AL float g_V[(size_t)NPTS * DIM];
__device__ AL bf16 g_VTh[(size_t)DIM * NPTS];
__device__ AL bf16 g_Eh[(size_t)NPTS * NPTS];
__device__ AL float g_csum[16 * NPTS];
__device__ AL float g_rc[NPTS];

__device__ __forceinline__ uint32_t smem_u32(const void* p) {
    uint32_t a;
    asm("{ .reg .u64 t; cvta.to.shared.u64 t, %1; cvt.u32.u64 %0, t; }" : "=r"(a) : "l"(p));
    return a;
}
__device__ __forceinline__ void cp16(uint32_t dst, const void* src) {
    asm volatile("cp.async.cg.shared.global [%0], [%1], 16;"
                 :: "r"(dst), "l"(__cvta_generic_to_global(src)) : "memory");
}
__device__ __forceinline__ void ldmx4(uint32_t* r, uint32_t addr) {
    asm volatile("ldmatrix.sync.aligned.m8n8.x4.shared.b16 {%0,%1,%2,%3}, [%4];"
                 : "=r"(r[0]), "=r"(r[1]), "=r"(r[2]), "=r"(r[3]) : "r"(addr));
}
__device__ __forceinline__ void mma16816(float* c, const uint32_t* a, const uint32_t* b) {
    asm volatile("mma.sync.aligned.m16n8k16.row.col.f32.bf16.bf16.f32 "
                 "{%0,%1,%2,%3}, {%4,%5,%6,%7}, {%8,%9}, {%0,%1,%2,%3};"
                 : "+f"(c[0]), "+f"(c[1]), "+f"(c[2]), "+f"(c[3])
                 : "r"(a[0]), "r"(a[1]), "r"(a[2]), "r"(a[3]), "r"(b[0]), "r"(b[1]));
}

// Tile: 128x128, BK=32 bf16 (64B rows). Swizzle: 16B chunk ^= (row>>1)&3.
// NPROD=3 stage: Ahi|Alo|Bhi|Blo = 32 KB. NPROD=1 stage: Ahi|Bhi = 16 KB. 3 stages.
#define BK 32
#define NSTG 3
#define GSMEM3 (3u * 32768u)
#define GSMEM1 (3u * 16384u)

__device__ __forceinline__ uint32_t swz(int row, int chunk) {
    return (uint32_t)(row * 64 + ((chunk ^ ((row >> 1) & 3)) << 4));
}

// MODE 0: bias+fp32 | 1: bias+bf16 split | 2: exp+bf16 hi only | 3: residual fp32
// NPROD 3: hi*hi + hi*lo + lo*hi | 1: hi*hi only
template <int MODE, int NPROD>
__global__ __launch_bounds__(256, 2) void gemm_mma(
    const bf16* __restrict__ Ahi, const bf16* __restrict__ Alo,
    const bf16* __restrict__ Bhi, const bf16* __restrict__ Blo,
    int Kd, int ldC, const float* __restrict__ bias, const float* __restrict__ P0,
    float* __restrict__ Cf, bf16* __restrict__ Chi, bf16* __restrict__ Clo)
{
    constexpr uint32_t STGB   = (NPROD == 1) ? 16384u : 32768u;
    constexpr uint32_t OF_ALO = 8192u;
    constexpr uint32_t OF_BHI = (NPROD == 1) ? 8192u : 16384u;
    constexpr uint32_t OF_BLO = 24576u;

    extern __shared__ char smraw[];
    const uint32_t sm0 = smem_u32(smraw);
    const int tid = threadIdx.x, lane = tid & 31, warp = tid >> 5;
    const int wm = warp >> 1, wn = warp & 1;           // 4 x 2 warp grid
    const int row0 = blockIdx.y * 128, col0 = blockIdx.x * 128;

    // per-thread ldmatrix offsets (within a tile)
    uint32_t aoff[2][2], boff[4][2];
#pragma unroll
    for (int mi = 0; mi < 2; mi++)
#pragma unroll
        for (int ks = 0; ks < 2; ks++) {
            const int r = wm * 32 + mi * 16 + (lane & 15);
            aoff[mi][ks] = swz(r, ks * 2 + (lane >> 4));
        }
#pragma unroll
    for (int np = 0; np < 4; np++)
#pragma unroll
        for (int ks = 0; ks < 2; ks++) {
            const int r = wn * 64 + np * 16 + (lane & 7) + ((lane >> 4) & 1) * 8;
            boff[np][ks] = swz(r, ks * 2 + ((lane >> 3) & 1));
        }

    // cp.async mapping: id = i*256+tid -> row=id>>2, chunk=id&3
    const int ldr = tid >> 2, ldc = tid & 3;

    auto load_stage = [&](int kb, int st) {
        const int k0 = kb * BK;
        const uint32_t s = sm0 + (uint32_t)st * STGB;
#pragma unroll
        for (int i = 0; i < 2; i++) {
            const int row = ldr + i * 64;
            const uint32_t d = swz(row, ldc);
            const size_t ga = (size_t)(row0 + row) * Kd + k0 + ldc * 8;
            const size_t gb = (size_t)(col0 + row) * Kd + k0 + ldc * 8;
            cp16(s + d, Ahi + ga);
            cp16(s + OF_BHI + d, Bhi + gb);
            if (NPROD == 3) {
                cp16(s + OF_ALO + d, Alo + ga);
                cp16(s + OF_BLO + d, Blo + gb);
            }
        }
    };

    float acc[2][8][4];
#pragma unroll
    for (int mi = 0; mi < 2; mi++)
#pragma unroll
        for (int ni = 0; ni < 8; ni++)
#pragma unroll
            for (int q = 0; q < 4; q++) acc[mi][ni][q] = 0.f;

    const int nkb = Kd / BK;
    load_stage(0, 0);
    asm volatile("cp.async.commit_group;" ::: "memory");
    load_stage(1, 1);
    asm volatile("cp.async.commit_group;" ::: "memory");

    int st = 0, pf = 2;   // current stage, prefetch stage
    for (int kb = 0; kb < nkb; kb++) {
        asm volatile("cp.async.wait_group 1;" ::: "memory");
        __syncthreads();
        // prefetch kb+2 into stage pf (its last readers were fenced by the sync)
        if (kb + 2 < nkb) load_stage(kb + 2, pf);
        asm volatile("cp.async.commit_group;" ::: "memory");

        const uint32_t s = sm0 + (uint32_t)st * STGB;
#pragma unroll
        for (int ks = 0; ks < 2; ks++) {
            uint32_t ah[2][4], al[2][4], bh[8][2], bl[8][2];
#pragma unroll
            for (int mi = 0; mi < 2; mi++) {
                ldmx4(ah[mi], s + aoff[mi][ks]);
                if (NPROD == 3) ldmx4(al[mi], s + OF_ALO + aoff[mi][ks]);
            }
#pragma unroll
            for (int np = 0; np < 4; np++) {
                uint32_t t[4];
                ldmx4(t, s + OF_BHI + boff[np][ks]);
                bh[np*2][0] = t[0]; bh[np*2][1] = t[1];
                bh[np*2+1][0] = t[2]; bh[np*2+1][1] = t[3];
                if (NPROD == 3) {
                    ldmx4(t, s + OF_BLO + boff[np][ks]);
                    bl[np*2][0] = t[0]; bl[np*2][1] = t[1];
                    bl[np*2+1][0] = t[2]; bl[np*2+1][1] = t[3];
                }
            }
#pragma unroll
            for (int mi = 0; mi < 2; mi++)
#pragma unroll
                for (int ni = 0; ni < 8; ni++)
                    mma16816(acc[mi][ni], ah[mi], bh[ni]);
            if (NPROD == 3) {
#pragma unroll
                for (int mi = 0; mi < 2; mi++)
#pragma unroll
                    for (int ni = 0; ni < 8; ni++)
                        mma16816(acc[mi][ni], ah[mi], bl[ni]);
#pragma unroll
                for (int mi = 0; mi < 2; mi++)
#pragma unroll
                    for (int ni = 0; ni < 8; ni++)
                        mma16816(acc[mi][ni], al[mi], bh[ni]);
            }
        }
        st = (st == NSTG - 1) ? 0 : st + 1;
        pf = (pf == NSTG - 1) ? 0 : pf + 1;
    }

    // Epilogue: frag (mi, ni): rows m0,m0+8; cols c0,c0+1
#pragma unroll
    for (int mi = 0; mi < 2; mi++)
#pragma unroll
        for (int ni = 0; ni < 8; ni++) {
            const int m0 = row0 + wm * 32 + mi * 16 + (lane >> 2);
            const int c  = col0 + wn * 64 + ni * 8 + (lane & 3) * 2;
#pragma unroll
            for (int h = 0; h < 2; h++) {
                const int m = m0 + h * 8;
                float v0 = acc[mi][ni][2 * h], v1 = acc[mi][ni][2 * h + 1];
                if (MODE == 0) {
                    float2* dst = (float2*)&Cf[(size_t)m * ldC + c];
                    *dst = make_float2(v0 + bias[c], v1 + bias[c + 1]);
                } else if (MODE == 3) {
                    const float2 pp = *(const float2*)&P0[(size_t)m * ldC + c];
                    float2* dst = (float2*)&Cf[(size_t)m * ldC + c];
                    *dst = make_float2(v0 + pp.x, v1 + pp.y);
                } else if (MODE == 2) {
                    // exp, bf16 hi only (lo dropped: averaging over 8192-term
                    // contraction keeps added error ~2e-5)
                    v0 = __expf(v0); v1 = __expf(v1);
                    *(__nv_bfloat162*)&Chi[(size_t)m * ldC + c] =
                        __nv_bfloat162(__float2bfloat16(v0), __float2bfloat16(v1));
                } else {  // MODE 1: bias + bf16 hi/lo split
                    v0 += bias[c]; v1 += bias[c + 1];
                    bf16 h0 = __float2bfloat16(v0), h1 = __float2bfloat16(v1);
                    *(__nv_bfloat162*)&Chi[(size_t)m * ldC + c] = __nv_bfloat162(h0, h1);
                    *(__nv_bfloat162*)&Clo[(size_t)m * ldC + c] =
                        __nv_bfloat162(__float2bfloat16(v0 - __bfloat162float(h0)),
                                       __float2bfloat16(v1 - __bfloat162float(h1)));
                }
            }
        }
}

__global__ __launch_bounds__(256) void split_kernel(
    const float4* __restrict__ x, __nv_bfloat162* __restrict__ hi,
    __nv_bfloat162* __restrict__ lo, int n4)
{
    int i = blockIdx.x * 256 + threadIdx.x;
    if (i >= n4) return;
    float4 v = x[i];
    bf16 h0 = __float2bfloat16(v.x), h1 = __float2bfloat16(v.y);
    bf16 h2 = __float2bfloat16(v.z), h3 = __float2bfloat16(v.w);
    hi[2*i]   = __nv_bfloat162(h0, h1);
    hi[2*i+1] = __nv_bfloat162(h2, h3);
    lo[2*i]   = __nv_bfloat162(__float2bfloat16(v.x - __bfloat162float(h0)),
                               __float2bfloat16(v.y - __bfloat162float(h1)));
    lo[2*i+1] = __nv_bfloat162(__float2bfloat16(v.z - __bfloat162float(h2)),
                               __float2bfloat16(v.w - __bfloat162float(h3)));
}

__global__ __launch_bounds__(256) void colsum_kernel(
    const bf16* __restrict__ Eh, float* __restrict__ csum)
{
    const int j = blockIdx.x * 256 + threadIdx.x;
    const size_t i0 = (size_t)blockIdx.y * (NPTS / 16);
    float c = 0.f;
    for (int t = 0; t < NPTS / 16; t++)
        c += __bfloat162float(Eh[(i0 + t) * NPTS + j]);
    csum[(size_t)blockIdx.y * NPTS + j] = c;
}

__global__ __launch_bounds__(256) void rc_kernel(
    const float* __restrict__ csum, float* __restrict__ rc)
{
    const int j = blockIdx.x * 256 + threadIdx.x;
    float c = 0.f;
#pragma unroll
    for (int h = 0; h < 16; h++) c += csum[(size_t)h * NPTS + j];
    rc[j] = 1.0f / c;
}

__global__ __launch_bounds__(256) void vt_kernel(
    const float* __restrict__ V, const float* __restrict__ rc,
    bf16* __restrict__ VTh)
{
    __shared__ float t[32][33];
    const int tx = threadIdx.x, ty = threadIdx.y;
    const int d0 = blockIdx.x * 32, j0 = blockIdx.y * 32;
#pragma unroll
    for (int q = 0; q < 4; q++) {
        const int j = j0 + ty + q * 8;
        t[ty + q * 8][tx] = V[(size_t)j * DIM + d0 + tx] * rc[j];
    }
    __syncthreads();
#pragma unroll
    for (int q = 0; q < 4; q++) {
        const int d = d0 + ty + q * 8, j = j0 + tx;
        VTh[(size_t)d * NPTS + j] = __float2bfloat16(t[tx][ty + q * 8]);
    }
}

extern "C" void kernel_launch(void* const* d_in, const int* in_sizes, int n_in,
                              void* d_out, int out_size)
{
    const float* p  = (const float*)d_in[0];
    const float* r  = (const float*)d_in[1];
    const float* Wh = (const float*)d_in[2];
    const float* bh = (const float*)d_in[3];
    const float* Wl = (const float*)d_in[4];
    const float* bl = (const float*)d_in[5];
    const float* Wg = (const float*)d_in[6];
    const float* bg = (const float*)d_in[7];
    float* out = (float*)d_out;

    bf16 *ph_, *pl_, *rh_, *rl_, *Whh, *Whl, *Wlh, *Wll, *Wgh, *Wgl;
    bf16 *Qh, *Ql, *Kh, *Kl, *VTh, *Eh;
    float *V, *csum, *rc;
    cudaGetSymbolAddress((void**)&ph_, g_ph);  cudaGetSymbolAddress((void**)&pl_, g_pl);
    cudaGetSymbolAddress((void**)&rh_, g_rh);  cudaGetSymbolAddress((void**)&rl_, g_rl);
    cudaGetSymbolAddress((void**)&Whh, g_Whh); cudaGetSymbolAddress((void**)&Whl, g_Whl);
    cudaGetSymbolAddress((void**)&Wlh, g_Wlh); cudaGetSymbolAddress((void**)&Wll, g_Wll);
    cudaGetSymbolAddress((void**)&Wgh, g_Wgh); cudaGetSymbolAddress((void**)&Wgl, g_Wgl);
    cudaGetSymbolAddress((void**)&Qh, g_Qh);   cudaGetSymbolAddress((void**)&Ql, g_Ql);
    cudaGetSymbolAddress((void**)&Kh, g_Kh);   cudaGetSymbolAddress((void**)&Kl, g_Kl);
    cudaGetSymbolAddress((void**)&V, g_V);
    cudaGetSymbolAddress((void**)&VTh, g_VTh);
    cudaGetSymbolAddress((void**)&Eh, g_Eh);
    cudaGetSymbolAddress((void**)&csum, g_csum); cudaGetSymbolAddress((void**)&rc, g_rc);

    cudaFuncSetAttribute(gemm_mma<0,3>, cudaFuncAttributeMaxDynamicSharedMemorySize, GSMEM3);
    cudaFuncSetAttribute(gemm_mma<1,3>, cudaFuncAttributeMaxDynamicSharedMemorySize, GSMEM3);
    cudaFuncSetAttribute(gemm_mma<2,3>, cudaFuncAttributeMaxDynamicSharedMemorySize, GSMEM3);
    cudaFuncSetAttribute(gemm_mma<3,1>, cudaFuncAttributeMaxDynamicSharedMemorySize, GSMEM1);

    const int nPD4 = NPTS * DIM / 4, nDD4 = DIM * DIM / 4;
    split_kernel<<<nPD4/256, 256>>>((const float4*)p, (__nv_bfloat162*)ph_, (__nv_bfloat162*)pl_, nPD4);
    split_kernel<<<nPD4/256, 256>>>((const float4*)r, (__nv_bfloat162*)rh_, (__nv_bfloat162*)rl_, nPD4);
    split_kernel<<<nDD4/256, 256>>>((const float4*)Wh, (__nv_bfloat162*)Whh, (__nv_bfloat162*)Whl, nDD4);
    split_kernel<<<nDD4/256, 256>>>((const float4*)Wl, (__nv_bfloat162*)Wlh, (__nv_bfloat162*)Wll, nDD4);
    split_kernel<<<nDD4/256, 256>>>((const float4*)Wg, (__nv_bfloat162*)Wgh, (__nv_bfloat162*)Wgl, nDD4);

    dim3 gproj(DIM/128, NPTS/128);
    gemm_mma<1,3><<<gproj, 256, GSMEM3>>>(ph_, pl_, Whh, Whl, DIM, DIM, bh, nullptr, nullptr, Qh, Ql);
    gemm_mma<1,3><<<gproj, 256, GSMEM3>>>(rh_, rl_, Wlh, Wll, DIM, DIM, bl, nullptr, nullptr, Kh, Kl);
    gemm_mma<0,3><<<gproj, 256, GSMEM3>>>(ph_, pl_, Wgh, Wgl, DIM, DIM, bg, nullptr, V, nullptr, nullptr);

    dim3 gS(NPTS/128, NPTS/128);
    gemm_mma<2,3><<<gS, 256, GSMEM3>>>(Qh, Ql, Kh, Kl, DIM, NPTS, nullptr, nullptr, nullptr, Eh, nullptr);

    colsum_kernel<<<dim3(NPTS/256, 16), 256>>>(Eh, csum);
    rc_kernel<<<NPTS/256, 256>>>(csum, rc);
    vt_kernel<<<dim3(DIM/32, NPTS/32), dim3(32, 8)>>>(V, rc, VTh);

    dim3 gpv(DIM/128, NPTS/128);
    gemm_mma<3,1><<<gpv, 256, GSMEM1>>>(Eh, nullptr, VTh, nullptr, NPTS, DIM, nullptr, p, out, nullptr, nullptr);
}